// round 11
// baseline (speedup 1.0000x reference)
#include <cuda_runtime.h>
#include <cuda_bf16.h>
#include <cstdint>

#define NN 64
#define CC 256
#define TT 64
#define VV 25
#define VP2 26
#define TVP (TT * VP2)            // 1664 padded cols = 13 x 128
#define NROWS (NN * CC * TT)
#define ELEMS26 (NROWS * VP2)

typedef unsigned long long ull;

// Device scratch (no cudaMalloc allowed)
__device__ float g_r0[ELEMS26];                  // residual ping (padded 26)
__device__ float g_r1[ELEMS26];                  // residual pong (padded 26)
__device__ __nv_bfloat16 g_yhi[ELEMS26];         // mixed, bf16 hi (padded 26)
__device__ __nv_bfloat16 g_ylo[ELEMS26];         // mixed, bf16 lo (padded 26)
__device__ __nv_bfloat16 g_whi[4 * CC * CC];
__device__ __nv_bfloat16 g_wlo[4 * CC * CC];

// ---------------- PTX helpers ----------------
__device__ __forceinline__ uint32_t smem_u32(const void* p) {
    uint32_t a;
    asm("{ .reg .u64 t; cvta.to.shared.u64 t, %1; cvt.u32.u64 %0, t; }" : "=r"(a) : "l"(p));
    return a;
}
__device__ __forceinline__ ull ffma2(ull a, ull b, ull c) {
    ull d; asm("fma.rn.f32x2 %0, %1, %2, %3;" : "=l"(d) : "l"(a), "l"(b), "l"(c)); return d;
}
__device__ __forceinline__ ull pack2(float x) {
    ull d; unsigned xu = __float_as_uint(x);
    asm("mov.b64 %0, {%1, %2};" : "=l"(d) : "r"(xu), "r"(xu)); return d;
}
__device__ __forceinline__ ull pack2f(float lo, float hi) {
    ull d; asm("mov.b64 %0, {%1, %2};" : "=l"(d) : "r"(__float_as_uint(lo)), "r"(__float_as_uint(hi))); return d;
}
__device__ __forceinline__ float lo32(ull a) { return __uint_as_float((unsigned)(a & 0xffffffffULL)); }
__device__ __forceinline__ float hi32(ull a) { return __uint_as_float((unsigned)(a >> 32)); }

__device__ __forceinline__ void ldsm_x4(uint32_t* r, uint32_t addr) {
    asm volatile("ldmatrix.sync.aligned.m8n8.x4.shared.b16 {%0,%1,%2,%3}, [%4];"
                 : "=r"(r[0]), "=r"(r[1]), "=r"(r[2]), "=r"(r[3]) : "r"(addr));
}
__device__ __forceinline__ void ldsm_x4_t(uint32_t* r, uint32_t addr) {
    asm volatile("ldmatrix.sync.aligned.m8n8.x4.trans.shared.b16 {%0,%1,%2,%3}, [%4];"
                 : "=r"(r[0]), "=r"(r[1]), "=r"(r[2]), "=r"(r[3]) : "r"(addr));
}
__device__ __forceinline__ void mma_bf16(float* c, const uint32_t* a, const uint32_t* b) {
    asm volatile("mma.sync.aligned.m16n8k16.row.col.f32.bf16.bf16.f32 "
                 "{%0,%1,%2,%3}, {%4,%5,%6,%7}, {%8,%9}, {%0,%1,%2,%3};"
                 : "+f"(c[0]), "+f"(c[1]), "+f"(c[2]), "+f"(c[3])
                 : "r"(a[0]), "r"(a[1]), "r"(a[2]), "r"(a[3]), "r"(b[0]), "r"(b[1]));
}
__device__ __forceinline__ void cp16(uint32_t dst, const void* src) {
    asm volatile("cp.async.cg.shared.global [%0], [%1], 16;" :: "r"(dst), "l"(src) : "memory");
}
#define CP_COMMIT() asm volatile("cp.async.commit_group;" ::: "memory")

// ---------------- W split kernel (once, all 4 layers) ----------------
__global__ void __launch_bounds__(256)
wsplit_kernel(const float* __restrict__ w0, const float* __restrict__ w1,
              const float* __restrict__ w2, const float* __restrict__ w3,
              __nv_bfloat16* __restrict__ whi, __nv_bfloat16* __restrict__ wlo)
{
    int id = blockIdx.x * 256 + threadIdx.x;
    const float* ws[4] = { w0, w1, w2, w3 };
    float v = ws[id >> 16][id & 65535];
    __nv_bfloat16 h = __float2bfloat16_rn(v);
    whi[id] = h;
    wlo[id] = __float2bfloat16_rn(v - __bfloat162float(h));
}

// ---------------- Mix: y = A-mix(res), emit bf16 hi/lo padded-26 ----------------
__global__ void __launch_bounds__(256)
mix_kernel(const float* __restrict__ in, const float* __restrict__ Amat,
           __nv_bfloat16* __restrict__ yhi, __nv_bfloat16* __restrict__ ylo,
           int sin)
{
    __shared__ float slab[6656];
    __shared__ ull sAp[325];
    const int tid = threadIdx.x;
    const int blk = blockIdx.x;

    for (int i = tid; i < 325; i += 256) {
        int u = i / 13, j = i - u * 13;
        float lo = Amat[(2 * j) * VV + u];
        float hi = (2 * j + 1 < VV) ? Amat[(2 * j + 1) * VV + u] : 0.f;
        sAp[i] = pack2f(lo, hi);
    }
    {
        const float4* src = (const float4*)(in + (size_t)blk * 256 * sin);
        const int n4 = (256 * sin) / 4;
        float4* dst = (float4*)slab;
        for (int i = tid; i < n4; i += 256) dst[i] = src[i];
    }
    __syncthreads();

    const int rb = tid * sin;
    float xr[VV];
#pragma unroll
    for (int u = 0; u < VV; u++) xr[u] = slab[rb + u];

    ull acc[13];
#pragma unroll
    for (int j = 0; j < 13; j++) acc[j] = 0ULL;
#pragma unroll
    for (int u = 0; u < VV; u++) {
        ull xu2 = pack2(xr[u]);
#pragma unroll
        for (int j = 0; j < 13; j++) acc[j] = ffma2(sAp[u * 13 + j], xu2, acc[j]);
    }
    __syncthreads();

    const int ob = tid * VP2;
#pragma unroll
    for (int j = 0; j < 13; j++) {
        slab[ob + 2 * j]     = lo32(acc[j]);
        slab[ob + 2 * j + 1] = hi32(acc[j]);   // j==12: hi == 0 via A pad row
    }
    __syncthreads();

    uint32_t* yh32 = (uint32_t*)yhi + (size_t)blk * 3328;
    uint32_t* yl32 = (uint32_t*)ylo + (size_t)blk * 3328;
    for (int i = tid; i < 3328; i += 256) {
        int row = i / 13, j = i - row * 13;
        float v0 = slab[row * VP2 + 2 * j];
        float v1 = slab[row * VP2 + 2 * j + 1];
        __nv_bfloat16 h0 = __float2bfloat16_rn(v0);
        __nv_bfloat16 h1 = __float2bfloat16_rn(v1);
        __nv_bfloat16 l0 = __float2bfloat16_rn(v0 - __bfloat162float(h0));
        __nv_bfloat16 l1 = __float2bfloat16_rn(v1 - __bfloat162float(h1));
        __nv_bfloat162 hh; hh.x = h0; hh.y = h1;
        __nv_bfloat162 ll; ll.x = l0; ll.y = l1;
        yh32[i] = *(uint32_t*)&hh;
        yl32[i] = *(uint32_t*)&ll;
    }
}

// ---------------- GEMM: out = relu(W @ y + b + res), 3xBF16 mma.sync ----------------
// grid (13, 2, 64). 3-stage cp.async pipeline, templated epilogue.
// MODE: 0 = res dense25 -> out padded26 (layer 0)
//       1 = padded26 -> padded26         (layers 1,2)
//       2 = padded26 -> out dense25      (layer 3)
#define WS_STRIDE 80
#define YS_STRIDE 272
#define SM_WH 0
#define SM_WL 10240
#define SM_YH 20480
#define SM_YL 29184
#define STAGE_BYTES 37888
#define NSTAGE 3
#define SM_TOTAL (NSTAGE * STAGE_BYTES)   // 113,664

template <int MODE>
__global__ void __launch_bounds__(256, 2)
gemm_kernel(const __nv_bfloat16* __restrict__ yhi, const __nv_bfloat16* __restrict__ ylo,
            const __nv_bfloat16* __restrict__ whi, const __nv_bfloat16* __restrict__ wlo,
            const float* __restrict__ bias, const float* __restrict__ res,
            float* __restrict__ out)
{
    extern __shared__ __align__(16) unsigned char smem[];
    const uint32_t smu = smem_u32(smem);

    const int tid  = threadIdx.x;
    const int lane = tid & 31, wid = tid >> 5;
    const int wm   = wid >> 1, wn = wid & 1;       // 4 (M) x 2 (N)
    const int ct   = blockIdx.x;
    const int mt   = blockIdx.y;
    const int n    = blockIdx.z;
    const int col0 = ct * 128;

    const __nv_bfloat16* Wh = whi + (size_t)(mt * 128) * CC;
    const __nv_bfloat16* Wl = wlo + (size_t)(mt * 128) * CC;
    const __nv_bfloat16* Yh = yhi + (size_t)n * CC * TVP + col0;
    const __nv_bfloat16* Yl = ylo + (size_t)n * CC * TVP + col0;

    // per-thread static load indices
    const int o_   = tid >> 2, cp4 = tid & 3;       // W round 1
    const int c_   = (tid + 256) >> 4, jp_ = tid & 15;   // (q=tid+256) mapping for Y? see below

    auto issue = [&](int kc) {
        const int c0 = kc * 32;
        const uint32_t sbase = smu + (kc % NSTAGE) * STAGE_BYTES;
        // W: 128 rows x 32 c, 512 cp16 per hl over 2 rounds
#pragma unroll
        for (int r = 0; r < 2; r++) {
            const int q = tid + r * 256;
            const int o = q >> 2, p = q & 3;
            const size_t wsrc = (size_t)o * CC + c0 + p * 8;
            const uint32_t wdst = sbase + o * WS_STRIDE + p * 16;
            cp16(wdst + SM_WH, Wh + wsrc);
            cp16(wdst + SM_WL, Wl + wsrc);
            const int c = q >> 4, jp = q & 15;
            const size_t ysrc = (size_t)(c0 + c) * TVP + jp * 8;
            const uint32_t ydst = sbase + c * YS_STRIDE + jp * 16;
            cp16(ydst + SM_YH, Yh + ysrc);
            cp16(ydst + SM_YL, Yl + ysrc);
        }
    };

    float acc[2][8][4];
#pragma unroll
    for (int fm = 0; fm < 2; fm++)
#pragma unroll
        for (int nb = 0; nb < 8; nb++)
#pragma unroll
            for (int q = 0; q < 4; q++) acc[fm][nb][q] = 0.f;

    issue(0); CP_COMMIT();
    issue(1); CP_COMMIT();

    for (int kc = 0; kc < 8; kc++) {
        if (kc + 2 < 8) {
            issue(kc + 2); CP_COMMIT();
            asm volatile("cp.async.wait_group 2;" ::: "memory");
        } else if (kc + 1 < 8) {
            asm volatile("cp.async.wait_group 1;" ::: "memory");
        } else {
            asm volatile("cp.async.wait_group 0;" ::: "memory");
        }
        __syncthreads();

        const uint32_t st  = smu + (kc % NSTAGE) * STAGE_BYTES;
        const uint32_t swh = st + SM_WH;
        const uint32_t swl = st + SM_WL;
        const uint32_t syh = st + SM_YH;
        const uint32_t syl = st + SM_YL;

#pragma unroll
        for (int s = 0; s < 2; s++) {
            uint32_t Ah[2][4], Al[2][4];
            const uint32_t aoff = (uint32_t)(lane & 15) * WS_STRIDE + s * 32 + (lane >> 4) * 16;
            ldsm_x4(Ah[0], swh + (wm * 32 +  0) * WS_STRIDE + aoff);
            ldsm_x4(Ah[1], swh + (wm * 32 + 16) * WS_STRIDE + aoff);
            ldsm_x4(Al[0], swl + (wm * 32 +  0) * WS_STRIDE + aoff);
            ldsm_x4(Al[1], swl + (wm * 32 + 16) * WS_STRIDE + aoff);

            const uint32_t boff = (uint32_t)(s * 16 + (lane & 15)) * YS_STRIDE + (lane >> 4) * 16;
#pragma unroll
            for (int nbp = 0; nbp < 4; nbp++) {
                uint32_t Bh[4], Bl[4];
                const uint32_t bcol = (uint32_t)(wn * 64 + nbp * 16) * 2;
                ldsm_x4_t(Bh, syh + boff + bcol);
                ldsm_x4_t(Bl, syl + boff + bcol);
#pragma unroll
                for (int h = 0; h < 2; h++) {
                    const int nb = nbp * 2 + h;
                    mma_bf16(acc[0][nb], Ah[0], &Bh[2 * h]);
                    mma_bf16(acc[0][nb], Ah[0], &Bl[2 * h]);
                    mma_bf16(acc[0][nb], Al[0], &Bh[2 * h]);
                    mma_bf16(acc[1][nb], Ah[1], &Bh[2 * h]);
                    mma_bf16(acc[1][nb], Ah[1], &Bl[2 * h]);
                    mma_bf16(acc[1][nb], Al[1], &Bh[2 * h]);
                }
            }
        }
        __syncthreads();
    }

    // ---- epilogue: relu(acc + b[o] + res) ----
    const int g = lane >> 2, tig = lane & 3;

#pragma unroll
    for (int fm = 0; fm < 2; fm++) {
        const int o0 = mt * 128 + wm * 32 + fm * 16 + g;
#pragma unroll
        for (int half = 0; half < 2; half++) {
            const int orow = o0 + half * 8;
            const float bs = bias[orow];
            const size_t rowb = (size_t)n * CC + orow;
#pragma unroll
            for (int nb = 0; nb < 8; nb++) {
                const int j = col0 + wn * 64 + nb * 8 + 2 * tig;
                const float a0 = acc[fm][nb][2 * half];
                const float a1 = acc[fm][nb][2 * half + 1];

                float r0v, r1v;
                if (MODE == 0) {
                    const int t0 = j / VP2, v0 = j - t0 * VP2;   // v0 even, v0+1 = v1 (j even)
                    const float* rp = res + ((rowb * TT + t0) * VV + v0);
                    r0v = (v0 < VV) ? rp[0] : 0.f;
                    r1v = (v0 + 1 < VV) ? rp[1] : 0.f;
                } else {
                    float2 rr = *(const float2*)(res + rowb * TVP + j);
                    r0v = rr.x; r1v = rr.y;
                }
                const float o0v = fmaxf(a0 + bs + r0v, 0.f);
                const float o1v = fmaxf(a1 + bs + r1v, 0.f);
                if (MODE == 2) {
                    const int t0 = j / VP2, v0 = j - t0 * VP2;
                    float* po = out + ((rowb * TT + t0) * VV + v0);
                    if (v0 < VV) po[0] = o0v;
                    if (v0 + 1 < VV) po[1] = o1v;
                } else {
                    *(float2*)(out + rowb * TVP + j) = make_float2(o0v, o1v);
                }
            }
        }
    }
}

// ---------------- launch ----------------
extern "C" void kernel_launch(void* const* d_in, const int* in_sizes, int n_in,
                              void* d_out, int out_size)
{
    // metadata order: t, x, A, w1, b1, w2, b2, w3, b3, w4, b4
    const float* x  = (const float*)d_in[1];
    const float* A  = (const float*)d_in[2];
    const float* W[4] = { (const float*)d_in[3], (const float*)d_in[5],
                          (const float*)d_in[7], (const float*)d_in[9] };
    const float* B[4] = { (const float*)d_in[4], (const float*)d_in[6],
                          (const float*)d_in[8], (const float*)d_in[10] };
    float* out = (float*)d_out;

    float *r0, *r1;
    __nv_bfloat16 *yhi, *ylo, *whi, *wlo;
    cudaGetSymbolAddress((void**)&r0,  g_r0);
    cudaGetSymbolAddress((void**)&r1,  g_r1);
    cudaGetSymbolAddress((void**)&yhi, g_yhi);
    cudaGetSymbolAddress((void**)&ylo, g_ylo);
    cudaGetSymbolAddress((void**)&whi, g_whi);
    cudaGetSymbolAddress((void**)&wlo, g_wlo);

    cudaFuncSetAttribute(gemm_kernel<0>,
                         cudaFuncAttributeMaxDynamicSharedMemorySize, SM_TOTAL);
    cudaFuncSetAttribute(gemm_kernel<1>,
                         cudaFuncAttributeMaxDynamicSharedMemorySize, SM_TOTAL);
    cudaFuncSetAttribute(gemm_kernel<2>,
                         cudaFuncAttributeMaxDynamicSharedMemorySize, SM_TOTAL);

    wsplit_kernel<<<1024, 256>>>(W[0], W[1], W[2], W[3], whi, wlo);

    dim3 ggrid(13, 2, NN);

    // layer 0: res = x (dense 25), out = r0 (padded)
    mix_kernel<<<NROWS / 256, 256>>>(x, A, yhi, ylo, 25);
    gemm_kernel<0><<<ggrid, 256, SM_TOTAL>>>(yhi, ylo, whi + 0 * CC * CC,
                                             wlo + 0 * CC * CC, B[0], x, r0);
    // layer 1: padded -> padded (r0 -> r1)
    mix_kernel<<<NROWS / 256, 256>>>(r0, A, yhi, ylo, 26);
    gemm_kernel<1><<<ggrid, 256, SM_TOTAL>>>(yhi, ylo, whi + 1 * CC * CC,
                                             wlo + 1 * CC * CC, B[1], r0, r1);
    // layer 2: padded -> padded (r1 -> r0)
    mix_kernel<<<NROWS / 256, 256>>>(r1, A, yhi, ylo, 26);
    gemm_kernel<1><<<ggrid, 256, SM_TOTAL>>>(yhi, ylo, whi + 2 * CC * CC,
                                             wlo + 2 * CC * CC, B[2], r1, r0);
    // layer 3: padded -> dense out
    mix_kernel<<<NROWS / 256, 256>>>(r0, A, yhi, ylo, 26);
    gemm_kernel<2><<<ggrid, 256, SM_TOTAL>>>(yhi, ylo, whi + 3 * CC * CC,
                                             wlo + 3 * CC * CC, B[3], r0, out);
}

// round 12
// speedup vs baseline: 1.1932x; 1.1932x over previous
#include <cuda_runtime.h>
#include <cuda_fp16.h>
#include <cstdint>

#define NN 64
#define CC 256
#define TT 64
#define VV 25
#define VP2 26
#define TVP (TT * VP2)            // 1664 padded cols = 13 x 128
#define NROWS (NN * CC * TT)
#define ELEMS26 (NROWS * VP2)

typedef unsigned long long ull;

// Device scratch (no cudaMalloc allowed)
__device__ float g_r0[ELEMS26];                  // residual ping (padded 26)
__device__ float g_r1[ELEMS26];                  // residual pong (padded 26)
__device__ __half g_yh[ELEMS26];                 // mixed, fp16 (padded 26)
__device__ __half g_whi[4 * CC * CC];            // W fp16 hi
__device__ __half g_wlo[4 * CC * CC];            // W fp16 lo

// ---------------- PTX helpers ----------------
__device__ __forceinline__ uint32_t smem_u32(const void* p) {
    uint32_t a;
    asm("{ .reg .u64 t; cvta.to.shared.u64 t, %1; cvt.u32.u64 %0, t; }" : "=r"(a) : "l"(p));
    return a;
}
__device__ __forceinline__ ull ffma2(ull a, ull b, ull c) {
    ull d; asm("fma.rn.f32x2 %0, %1, %2, %3;" : "=l"(d) : "l"(a), "l"(b), "l"(c)); return d;
}
__device__ __forceinline__ ull pack2(float x) {
    ull d; unsigned xu = __float_as_uint(x);
    asm("mov.b64 %0, {%1, %2};" : "=l"(d) : "r"(xu), "r"(xu)); return d;
}
__device__ __forceinline__ ull pack2f(float lo, float hi) {
    ull d; asm("mov.b64 %0, {%1, %2};" : "=l"(d) : "r"(__float_as_uint(lo)), "r"(__float_as_uint(hi))); return d;
}
__device__ __forceinline__ float lo32(ull a) { return __uint_as_float((unsigned)(a & 0xffffffffULL)); }
__device__ __forceinline__ float hi32(ull a) { return __uint_as_float((unsigned)(a >> 32)); }

__device__ __forceinline__ void ldsm_x4(uint32_t* r, uint32_t addr) {
    asm volatile("ldmatrix.sync.aligned.m8n8.x4.shared.b16 {%0,%1,%2,%3}, [%4];"
                 : "=r"(r[0]), "=r"(r[1]), "=r"(r[2]), "=r"(r[3]) : "r"(addr));
}
__device__ __forceinline__ void ldsm_x4_t(uint32_t* r, uint32_t addr) {
    asm volatile("ldmatrix.sync.aligned.m8n8.x4.trans.shared.b16 {%0,%1,%2,%3}, [%4];"
                 : "=r"(r[0]), "=r"(r[1]), "=r"(r[2]), "=r"(r[3]) : "r"(addr));
}
__device__ __forceinline__ void mma_f16(float* c, const uint32_t* a, const uint32_t* b) {
    asm volatile("mma.sync.aligned.m16n8k16.row.col.f32.f16.f16.f32 "
                 "{%0,%1,%2,%3}, {%4,%5,%6,%7}, {%8,%9}, {%0,%1,%2,%3};"
                 : "+f"(c[0]), "+f"(c[1]), "+f"(c[2]), "+f"(c[3])
                 : "r"(a[0]), "r"(a[1]), "r"(a[2]), "r"(a[3]), "r"(b[0]), "r"(b[1]));
}
__device__ __forceinline__ void cp16(uint32_t dst, const void* src) {
    asm volatile("cp.async.cg.shared.global [%0], [%1], 16;" :: "r"(dst), "l"(src) : "memory");
}
#define CP_COMMIT() asm volatile("cp.async.commit_group;" ::: "memory")

// ---------------- W split kernel (once, all 4 layers) ----------------
__global__ void __launch_bounds__(256)
wsplit_kernel(const float* __restrict__ w0, const float* __restrict__ w1,
              const float* __restrict__ w2, const float* __restrict__ w3,
              __half* __restrict__ whi, __half* __restrict__ wlo)
{
    int id = blockIdx.x * 256 + threadIdx.x;
    const float* ws[4] = { w0, w1, w2, w3 };
    float v = ws[id >> 16][id & 65535];
    __half h = __float2half_rn(v);
    whi[id] = h;
    wlo[id] = __float2half_rn(v - __half2float(h));
}

// ---------------- Mix: y = A-mix(res), emit fp16 padded-26 ----------------
__global__ void __launch_bounds__(256)
mix_kernel(const float* __restrict__ in, const float* __restrict__ Amat,
           __half* __restrict__ yh, int sin)
{
    __shared__ float slab[6656];
    __shared__ ull sAp[325];
    const int tid = threadIdx.x;
    const int blk = blockIdx.x;

    for (int i = tid; i < 325; i += 256) {
        int u = i / 13, j = i - u * 13;
        float lo = Amat[(2 * j) * VV + u];
        float hi = (2 * j + 1 < VV) ? Amat[(2 * j + 1) * VV + u] : 0.f;
        sAp[i] = pack2f(lo, hi);
    }
    {
        const float4* src = (const float4*)(in + (size_t)blk * 256 * sin);
        const int n4 = (256 * sin) / 4;
        float4* dst = (float4*)slab;
        for (int i = tid; i < n4; i += 256) dst[i] = src[i];
    }
    __syncthreads();

    const int rb = tid * sin;
    float xr[VV];
#pragma unroll
    for (int u = 0; u < VV; u++) xr[u] = slab[rb + u];

    ull acc[13];
#pragma unroll
    for (int j = 0; j < 13; j++) acc[j] = 0ULL;
#pragma unroll
    for (int u = 0; u < VV; u++) {
        ull xu2 = pack2(xr[u]);
#pragma unroll
        for (int j = 0; j < 13; j++) acc[j] = ffma2(sAp[u * 13 + j], xu2, acc[j]);
    }
    __syncthreads();

    const int ob = tid * VP2;
#pragma unroll
    for (int j = 0; j < 13; j++) {
        slab[ob + 2 * j]     = lo32(acc[j]);
        slab[ob + 2 * j + 1] = hi32(acc[j]);   // j==12: hi == 0 via A pad row
    }
    __syncthreads();

    uint32_t* yh32 = (uint32_t*)yh + (size_t)blk * 3328;
    for (int i = tid; i < 3328; i += 256) {
        int row = i / 13, j = i - row * 13;
        float v0 = slab[row * VP2 + 2 * j];
        float v1 = slab[row * VP2 + 2 * j + 1];
        __half2 hh = __floats2half2_rn(v0, v1);
        yh32[i] = *(uint32_t*)&hh;
    }
}

// ---------------- GEMM: out = relu((Wh+Wl) @ Yh + b + res), fp16 mma.sync ----------------
// grid (13, 2, 64). 3-stage cp.async pipeline, templated epilogue.
// MODE: 0 = res dense25 -> out padded26 (layer 0)
//       1 = padded26 -> padded26         (layers 1,2)
//       2 = padded26 -> out dense25      (layer 3)
#define WS_STRIDE 80
#define YS_STRIDE 272
#define SM_WH 0
#define SM_WL 10240
#define SM_YH 20480
#define STAGE_BYTES 29184
#define NSTAGE 3
#define SM_TOTAL (NSTAGE * STAGE_BYTES)   // 87,552

template <int MODE>
__global__ void __launch_bounds__(256, 2)
gemm_kernel(const __half* __restrict__ yh,
            const __half* __restrict__ whi, const __half* __restrict__ wlo,
            const float* __restrict__ bias, const float* __restrict__ res,
            float* __restrict__ out)
{
    extern __shared__ __align__(16) unsigned char smem[];
    const uint32_t smu = smem_u32(smem);

    const int tid  = threadIdx.x;
    const int lane = tid & 31, wid = tid >> 5;
    const int wm   = wid >> 1, wn = wid & 1;       // 4 (M) x 2 (N)
    const int ct   = blockIdx.x;
    const int mt   = blockIdx.y;
    const int n    = blockIdx.z;
    const int col0 = ct * 128;

    const __half* Wh = whi + (size_t)(mt * 128) * CC;
    const __half* Wl = wlo + (size_t)(mt * 128) * CC;
    const __half* Yh = yh  + (size_t)n * CC * TVP + col0;

    auto issue = [&](int kc) {
        const int c0 = kc * 32;
        const uint32_t sbase = smu + (kc % NSTAGE) * STAGE_BYTES;
#pragma unroll
        for (int r = 0; r < 2; r++) {
            const int q = tid + r * 256;
            // W: 128 rows x 32 c, hi+lo
            const int o = q >> 2, p = q & 3;
            const size_t wsrc = (size_t)o * CC + c0 + p * 8;
            const uint32_t wdst = sbase + o * WS_STRIDE + p * 16;
            cp16(wdst + SM_WH, Wh + wsrc);
            cp16(wdst + SM_WL, Wl + wsrc);
            // Y: 32 c x 128 j, hi only
            const int c = q >> 4, jp = q & 15;
            const size_t ysrc = (size_t)(c0 + c) * TVP + jp * 8;
            cp16(sbase + SM_YH + c * YS_STRIDE + jp * 16, Yh + ysrc);
        }
    };

    float acc[2][8][4];
#pragma unroll
    for (int fm = 0; fm < 2; fm++)
#pragma unroll
        for (int nb = 0; nb < 8; nb++)
#pragma unroll
            for (int q = 0; q < 4; q++) acc[fm][nb][q] = 0.f;

    issue(0); CP_COMMIT();
    issue(1); CP_COMMIT();

    for (int kc = 0; kc < 8; kc++) {
        if (kc + 2 < 8) {
            issue(kc + 2); CP_COMMIT();
            asm volatile("cp.async.wait_group 2;" ::: "memory");
        } else if (kc + 1 < 8) {
            asm volatile("cp.async.wait_group 1;" ::: "memory");
        } else {
            asm volatile("cp.async.wait_group 0;" ::: "memory");
        }
        __syncthreads();

        const uint32_t st  = smu + (kc % NSTAGE) * STAGE_BYTES;
        const uint32_t swh = st + SM_WH;
        const uint32_t swl = st + SM_WL;
        const uint32_t syh = st + SM_YH;

#pragma unroll
        for (int s = 0; s < 2; s++) {
            uint32_t Ah[2][4], Al[2][4];
            const uint32_t aoff = (uint32_t)(lane & 15) * WS_STRIDE + s * 32 + (lane >> 4) * 16;
            ldsm_x4(Ah[0], swh + (wm * 32 +  0) * WS_STRIDE + aoff);
            ldsm_x4(Ah[1], swh + (wm * 32 + 16) * WS_STRIDE + aoff);
            ldsm_x4(Al[0], swl + (wm * 32 +  0) * WS_STRIDE + aoff);
            ldsm_x4(Al[1], swl + (wm * 32 + 16) * WS_STRIDE + aoff);

            const uint32_t boff = (uint32_t)(s * 16 + (lane & 15)) * YS_STRIDE + (lane >> 4) * 16;
#pragma unroll
            for (int nbp = 0; nbp < 4; nbp++) {
                uint32_t Bh[4];
                const uint32_t bcol = (uint32_t)(wn * 64 + nbp * 16) * 2;
                ldsm_x4_t(Bh, syh + boff + bcol);
#pragma unroll
                for (int h = 0; h < 2; h++) {
                    const int nb = nbp * 2 + h;
                    mma_f16(acc[0][nb], Ah[0], &Bh[2 * h]);
                    mma_f16(acc[0][nb], Al[0], &Bh[2 * h]);
                    mma_f16(acc[1][nb], Ah[1], &Bh[2 * h]);
                    mma_f16(acc[1][nb], Al[1], &Bh[2 * h]);
                }
            }
        }
        __syncthreads();
    }

    // ---- epilogue: relu(acc + b[o] + res) ----
    const int g = lane >> 2, tig = lane & 3;

#pragma unroll
    for (int fm = 0; fm < 2; fm++) {
        const int o0 = mt * 128 + wm * 32 + fm * 16 + g;
#pragma unroll
        for (int half = 0; half < 2; half++) {
            const int orow = o0 + half * 8;
            const float bs = bias[orow];
            const size_t rowb = (size_t)n * CC + orow;
#pragma unroll
            for (int nb = 0; nb < 8; nb++) {
                const int j = col0 + wn * 64 + nb * 8 + 2 * tig;
                const float a0 = acc[fm][nb][2 * half];
                const float a1 = acc[fm][nb][2 * half + 1];

                float r0v, r1v;
                if (MODE == 0) {
                    const int t0 = j / VP2, v0 = j - t0 * VP2;
                    const float* rp = res + ((rowb * TT + t0) * VV + v0);
                    r0v = (v0 < VV) ? rp[0] : 0.f;
                    r1v = (v0 + 1 < VV) ? rp[1] : 0.f;
                } else {
                    float2 rr = *(const float2*)(res + rowb * TVP + j);
                    r0v = rr.x; r1v = rr.y;
                }
                const float o0v = fmaxf(a0 + bs + r0v, 0.f);
                const float o1v = fmaxf(a1 + bs + r1v, 0.f);
                if (MODE == 2) {
                    const int t0 = j / VP2, v0 = j - t0 * VP2;
                    float* po = out + ((rowb * TT + t0) * VV + v0);
                    if (v0 < VV) po[0] = o0v;
                    if (v0 + 1 < VV) po[1] = o1v;
                } else {
                    *(float2*)(out + rowb * TVP + j) = make_float2(o0v, o1v);
                }
            }
        }
    }
}

// ---------------- launch ----------------
extern "C" void kernel_launch(void* const* d_in, const int* in_sizes, int n_in,
                              void* d_out, int out_size)
{
    // metadata order: t, x, A, w1, b1, w2, b2, w3, b3, w4, b4
    const float* x  = (const float*)d_in[1];
    const float* A  = (const float*)d_in[2];
    const float* W[4] = { (const float*)d_in[3], (const float*)d_in[5],
                          (const float*)d_in[7], (const float*)d_in[9] };
    const float* B[4] = { (const float*)d_in[4], (const float*)d_in[6],
                          (const float*)d_in[8], (const float*)d_in[10] };
    float* out = (float*)d_out;

    float *r0, *r1;
    __half *yh, *whi, *wlo;
    cudaGetSymbolAddress((void**)&r0,  g_r0);
    cudaGetSymbolAddress((void**)&r1,  g_r1);
    cudaGetSymbolAddress((void**)&yh,  g_yh);
    cudaGetSymbolAddress((void**)&whi, g_whi);
    cudaGetSymbolAddress((void**)&wlo, g_wlo);

    cudaFuncSetAttribute(gemm_kernel<0>,
                         cudaFuncAttributeMaxDynamicSharedMemorySize, SM_TOTAL);
    cudaFuncSetAttribute(gemm_kernel<1>,
                         cudaFuncAttributeMaxDynamicSharedMemorySize, SM_TOTAL);
    cudaFuncSetAttribute(gemm_kernel<2>,
                         cudaFuncAttributeMaxDynamicSharedMemorySize, SM_TOTAL);

    wsplit_kernel<<<1024, 256>>>(W[0], W[1], W[2], W[3], whi, wlo);

    dim3 ggrid(13, 2, NN);

    // layer 0: res = x (dense 25), out = r0 (padded)
    mix_kernel<<<NROWS / 256, 256>>>(x, A, yh, 25);
    gemm_kernel<0><<<ggrid, 256, SM_TOTAL>>>(yh, whi + 0 * CC * CC,
                                             wlo + 0 * CC * CC, B[0], x, r0);
    // layer 1: padded -> padded (r0 -> r1)
    mix_kernel<<<NROWS / 256, 256>>>(r0, A, yh, 26);
    gemm_kernel<1><<<ggrid, 256, SM_TOTAL>>>(yh, whi + 1 * CC * CC,
                                             wlo + 1 * CC * CC, B[1], r0, r1);
    // layer 2: padded -> padded (r1 -> r0)
    mix_kernel<<<NROWS / 256, 256>>>(r1, A, yh, 26);
    gemm_kernel<1><<<ggrid, 256, SM_TOTAL>>>(yh, whi + 2 * CC * CC,
                                             wlo + 2 * CC * CC, B[2], r1, r0);
    // layer 3: padded -> dense out
    mix_kernel<<<NROWS / 256, 256>>>(r0, A, yh, 26);
    gemm_kernel<2><<<ggrid, 256, SM_TOTAL>>>(yh, whi + 3 * CC * CC,
                                             wlo + 3 * CC * CC, B[3], r0, out);
}

// round 13
// speedup vs baseline: 1.2651x; 1.0602x over previous
#include <cuda_runtime.h>
#include <cuda_fp16.h>
#include <cstdint>

#define NN 64
#define CC 256
#define TT 64
#define VV 25
#define VP2 26
#define TVP (TT * VP2)            // 1664 padded cols = 13 x 128
#define NROWS (NN * CC * TT)
#define ELEMS26 (NROWS * VP2)

typedef unsigned long long ull;

// Device scratch (no cudaMalloc allowed)
__device__ float g_r0[ELEMS26];                  // residual ping (padded 26)
__device__ float g_r1[ELEMS26];                  // residual pong (padded 26)
__device__ __half g_yh[ELEMS26];                 // mixed, fp16 (padded 26)
__device__ __half g_whi[4 * CC * CC];            // W fp16 hi
__device__ __half g_wlo[4 * CC * CC];            // W fp16 lo

// ---------------- PTX helpers ----------------
__device__ __forceinline__ uint32_t smem_u32(const void* p) {
    uint32_t a;
    asm("{ .reg .u64 t; cvta.to.shared.u64 t, %1; cvt.u32.u64 %0, t; }" : "=r"(a) : "l"(p));
    return a;
}
__device__ __forceinline__ ull ffma2(ull a, ull b, ull c) {
    ull d; asm("fma.rn.f32x2 %0, %1, %2, %3;" : "=l"(d) : "l"(a), "l"(b), "l"(c)); return d;
}
__device__ __forceinline__ ull pack2(float x) {
    ull d; unsigned xu = __float_as_uint(x);
    asm("mov.b64 %0, {%1, %2};" : "=l"(d) : "r"(xu), "r"(xu)); return d;
}
__device__ __forceinline__ ull pack2f(float lo, float hi) {
    ull d; asm("mov.b64 %0, {%1, %2};" : "=l"(d) : "r"(__float_as_uint(lo)), "r"(__float_as_uint(hi))); return d;
}
__device__ __forceinline__ float lo32(ull a) { return __uint_as_float((unsigned)(a & 0xffffffffULL)); }
__device__ __forceinline__ float hi32(ull a) { return __uint_as_float((unsigned)(a >> 32)); }

__device__ __forceinline__ void ldsm_x4(uint32_t* r, uint32_t addr) {
    asm volatile("ldmatrix.sync.aligned.m8n8.x4.shared.b16 {%0,%1,%2,%3}, [%4];"
                 : "=r"(r[0]), "=r"(r[1]), "=r"(r[2]), "=r"(r[3]) : "r"(addr));
}
__device__ __forceinline__ void ldsm_x4_t(uint32_t* r, uint32_t addr) {
    asm volatile("ldmatrix.sync.aligned.m8n8.x4.trans.shared.b16 {%0,%1,%2,%3}, [%4];"
                 : "=r"(r[0]), "=r"(r[1]), "=r"(r[2]), "=r"(r[3]) : "r"(addr));
}
__device__ __forceinline__ void mma_f16(float* c, const uint32_t* a, const uint32_t* b) {
    asm volatile("mma.sync.aligned.m16n8k16.row.col.f32.f16.f16.f32 "
                 "{%0,%1,%2,%3}, {%4,%5,%6,%7}, {%8,%9}, {%0,%1,%2,%3};"
                 : "+f"(c[0]), "+f"(c[1]), "+f"(c[2]), "+f"(c[3])
                 : "r"(a[0]), "r"(a[1]), "r"(a[2]), "r"(a[3]), "r"(b[0]), "r"(b[1]));
}
__device__ __forceinline__ void cp16(uint32_t dst, const void* src) {
    asm volatile("cp.async.cg.shared.global [%0], [%1], 16;" :: "r"(dst), "l"(src) : "memory");
}
#define CP_COMMIT() asm volatile("cp.async.commit_group;" ::: "memory")

// ---------------- W split kernel (once, all 4 layers) ----------------
__global__ void __launch_bounds__(256)
wsplit_kernel(const float* __restrict__ w0, const float* __restrict__ w1,
              const float* __restrict__ w2, const float* __restrict__ w3,
              __half* __restrict__ whi, __half* __restrict__ wlo)
{
    int id = blockIdx.x * 256 + threadIdx.x;
    const float* ws[4] = { w0, w1, w2, w3 };
    float v = ws[id >> 16][id & 65535];
    __half h = __float2half_rn(v);
    whi[id] = h;
    wlo[id] = __float2half_rn(v - __half2float(h));
}

// ---------------- Mix: y = A-mix(res), emit fp16 padded-26 ----------------
__global__ void __launch_bounds__(256)
mix_kernel(const float* __restrict__ in, const float* __restrict__ Amat,
           __half* __restrict__ yh, int sin)
{
    __shared__ __align__(16) float slab[6656];
    __shared__ ull sAp[325];
    const int tid = threadIdx.x;
    const int blk = blockIdx.x;

    for (int i = tid; i < 325; i += 256) {
        int u = i / 13, j = i - u * 13;
        float lo = Amat[(2 * j) * VV + u];
        float hi = (2 * j + 1 < VV) ? Amat[(2 * j + 1) * VV + u] : 0.f;
        sAp[i] = pack2f(lo, hi);
    }
    {
        const float4* src = (const float4*)(in + (size_t)blk * 256 * sin);
        const int n4 = (256 * sin) / 4;
        float4* dst = (float4*)slab;
        for (int i = tid; i < n4; i += 256) dst[i] = src[i];
    }
    __syncthreads();

    const int rb = tid * sin;
    float xr[VV];
#pragma unroll
    for (int u = 0; u < VV; u++) xr[u] = slab[rb + u];

    ull acc[13];
#pragma unroll
    for (int j = 0; j < 13; j++) acc[j] = 0ULL;
#pragma unroll
    for (int u = 0; u < VV; u++) {
        ull xu2 = pack2(xr[u]);
#pragma unroll
        for (int j = 0; j < 13; j++) acc[j] = ffma2(sAp[u * 13 + j], xu2, acc[j]);
    }
    __syncthreads();

    // store packed accumulators as 13 x STS.64 (row = 26 floats = 13 ull)
    {
        ull* so = (ull*)slab + tid * 13;
#pragma unroll
        for (int j = 0; j < 13; j++) so[j] = acc[j];   // j==12 hi == 0 via A pad row
    }
    __syncthreads();

    // emit: LDS.128 + convert + STG.64, 1664 per CTA
    {
        ull* yh64 = (ull*)((uint32_t*)yh + (size_t)blk * 3328);
        const float4* sf4 = (const float4*)slab;
        for (int i = tid; i < 1664; i += 256) {
            float4 v = sf4[i];
            __half2 a = __floats2half2_rn(v.x, v.y);
            __half2 b = __floats2half2_rn(v.z, v.w);
            uint32_t ua = *(uint32_t*)&a;
            uint32_t ub = *(uint32_t*)&b;
            yh64[i] = (ull)ua | ((ull)ub << 32);
        }
    }
}

// ---------------- GEMM: out = relu((Wh+Wl) @ Yh + b + res), fp16 mma.sync ----------------
// grid (13, 2, 64). 3-stage cp.async pipeline, ONE barrier per k-chunk.
// MODE: 0 = res dense25 -> out padded26 (layer 0)
//       1 = padded26 -> padded26         (layers 1,2)
//       2 = padded26 -> out dense25      (layer 3)
#define WS_STRIDE 80
#define YS_STRIDE 272
#define SM_WH 0
#define SM_WL 10240
#define SM_YH 20480
#define STAGE_BYTES 29184
#define NSTAGE 3
#define SM_TOTAL (NSTAGE * STAGE_BYTES)   // 87,552

template <int MODE>
__global__ void __launch_bounds__(256, 2)
gemm_kernel(const __half* __restrict__ yh,
            const __half* __restrict__ whi, const __half* __restrict__ wlo,
            const float* __restrict__ bias, const float* __restrict__ res,
            float* __restrict__ out)
{
    extern __shared__ __align__(16) unsigned char smem[];
    const uint32_t smu = smem_u32(smem);

    const int tid  = threadIdx.x;
    const int lane = tid & 31, wid = tid >> 5;
    const int wm   = wid >> 1, wn = wid & 1;       // 4 (M) x 2 (N)
    const int ct   = blockIdx.x;
    const int mt   = blockIdx.y;
    const int n    = blockIdx.z;
    const int col0 = ct * 128;

    const __half* Wh = whi + (size_t)(mt * 128) * CC;
    const __half* Wl = wlo + (size_t)(mt * 128) * CC;
    const __half* Yh = yh  + (size_t)n * CC * TVP + col0;

    auto issue = [&](int kc) {
        const int c0 = kc * 32;
        const uint32_t sbase = smu + (kc % NSTAGE) * STAGE_BYTES;
#pragma unroll
        for (int r = 0; r < 2; r++) {
            const int q = tid + r * 256;
            const int o = q >> 2, p = q & 3;
            const size_t wsrc = (size_t)o * CC + c0 + p * 8;
            const uint32_t wdst = sbase + o * WS_STRIDE + p * 16;
            cp16(wdst + SM_WH, Wh + wsrc);
            cp16(wdst + SM_WL, Wl + wsrc);
            const int c = q >> 4, jp = q & 15;
            const size_t ysrc = (size_t)(c0 + c) * TVP + jp * 8;
            cp16(sbase + SM_YH + c * YS_STRIDE + jp * 16, Yh + ysrc);
        }
    };

    float acc[2][8][4];
#pragma unroll
    for (int fm = 0; fm < 2; fm++)
#pragma unroll
        for (int nb = 0; nb < 8; nb++)
#pragma unroll
            for (int q = 0; q < 4; q++) acc[fm][nb][q] = 0.f;

    issue(0); CP_COMMIT();
    issue(1); CP_COMMIT();

    for (int kc = 0; kc < 8; kc++) {
        // wait for stage kc data (all groups up to kc complete)
        if (kc + 1 < 8) {
            asm volatile("cp.async.wait_group 1;" ::: "memory");
        } else {
            asm volatile("cp.async.wait_group 0;" ::: "memory");
        }
        __syncthreads();   // also guarantees all readers of stage (kc-1)%3 are done

        if (kc + 2 < 8) {
            issue(kc + 2);   // overwrites stage (kc-1)%3 — safe after the sync
            CP_COMMIT();
        }

        const uint32_t st  = smu + (kc % NSTAGE) * STAGE_BYTES;
        const uint32_t swh = st + SM_WH;
        const uint32_t swl = st + SM_WL;
        const uint32_t syh = st + SM_YH;

#pragma unroll
        for (int s = 0; s < 2; s++) {
            uint32_t Ah[2][4], Al[2][4];
            const uint32_t aoff = (uint32_t)(lane & 15) * WS_STRIDE + s * 32 + (lane >> 4) * 16;
            ldsm_x4(Ah[0], swh + (wm * 32 +  0) * WS_STRIDE + aoff);
            ldsm_x4(Ah[1], swh + (wm * 32 + 16) * WS_STRIDE + aoff);
            ldsm_x4(Al[0], swl + (wm * 32 +  0) * WS_STRIDE + aoff);
            ldsm_x4(Al[1], swl + (wm * 32 + 16) * WS_STRIDE + aoff);

            const uint32_t boff = (uint32_t)(s * 16 + (lane & 15)) * YS_STRIDE + (lane >> 4) * 16;
#pragma unroll
            for (int nbp = 0; nbp < 4; nbp++) {
                uint32_t Bh[4];
                const uint32_t bcol = (uint32_t)(wn * 64 + nbp * 16) * 2;
                ldsm_x4_t(Bh, syh + boff + bcol);
#pragma unroll
                for (int h = 0; h < 2; h++) {
                    const int nb = nbp * 2 + h;
                    mma_f16(acc[0][nb], Ah[0], &Bh[2 * h]);
                    mma_f16(acc[0][nb], Al[0], &Bh[2 * h]);
                    mma_f16(acc[1][nb], Ah[1], &Bh[2 * h]);
                    mma_f16(acc[1][nb], Al[1], &Bh[2 * h]);
                }
            }
        }
        // no trailing barrier: next iteration's top sync provides it
    }

    // ---- epilogue: relu(acc + b[o] + res) ----
    const int g = lane >> 2, tig = lane & 3;

#pragma unroll
    for (int fm = 0; fm < 2; fm++) {
        const int o0 = mt * 128 + wm * 32 + fm * 16 + g;
#pragma unroll
        for (int half = 0; half < 2; half++) {
            const int orow = o0 + half * 8;
            const float bs = bias[orow];
            const size_t rowb = (size_t)n * CC + orow;
#pragma unroll
            for (int nb = 0; nb < 8; nb++) {
                const int j = col0 + wn * 64 + nb * 8 + 2 * tig;
                const float a0 = acc[fm][nb][2 * half];
                const float a1 = acc[fm][nb][2 * half + 1];

                float r0v, r1v;
                if (MODE == 0) {
                    const int t0 = j / VP2, v0 = j - t0 * VP2;
                    const float* rp = res + ((rowb * TT + t0) * VV + v0);
                    r0v = (v0 < VV) ? rp[0] : 0.f;
                    r1v = (v0 + 1 < VV) ? rp[1] : 0.f;
                } else {
                    float2 rr = *(const float2*)(res + rowb * TVP + j);
                    r0v = rr.x; r1v = rr.y;
                }
                const float o0v = fmaxf(a0 + bs + r0v, 0.f);
                const float o1v = fmaxf(a1 + bs + r1v, 0.f);
                if (MODE == 2) {
                    const int t0 = j / VP2, v0 = j - t0 * VP2;
                    float* po = out + ((rowb * TT + t0) * VV + v0);
                    if (v0 < VV) po[0] = o0v;
                    if (v0 + 1 < VV) po[1] = o1v;
                } else {
                    *(float2*)(out + rowb * TVP + j) = make_float2(o0v, o1v);
                }
            }
        }
    }
}

// ---------------- launch ----------------
extern "C" void kernel_launch(void* const* d_in, const int* in_sizes, int n_in,
                              void* d_out, int out_size)
{
    // metadata order: t, x, A, w1, b1, w2, b2, w3, b3, w4, b4
    const float* x  = (const float*)d_in[1];
    const float* A  = (const float*)d_in[2];
    const float* W[4] = { (const float*)d_in[3], (const float*)d_in[5],
                          (const float*)d_in[7], (const float*)d_in[9] };
    const float* B[4] = { (const float*)d_in[4], (const float*)d_in[6],
                          (const float*)d_in[8], (const float*)d_in[10] };
    float* out = (float*)d_out;

    float *r0, *r1;
    __half *yh, *whi, *wlo;
    cudaGetSymbolAddress((void**)&r0,  g_r0);
    cudaGetSymbolAddress((void**)&r1,  g_r1);
    cudaGetSymbolAddress((void**)&yh,  g_yh);
    cudaGetSymbolAddress((void**)&whi, g_whi);
    cudaGetSymbolAddress((void**)&wlo, g_wlo);

    cudaFuncSetAttribute(gemm_kernel<0>,
                         cudaFuncAttributeMaxDynamicSharedMemorySize, SM_TOTAL);
    cudaFuncSetAttribute(gemm_kernel<1>,
                         cudaFuncAttributeMaxDynamicSharedMemorySize, SM_TOTAL);
    cudaFuncSetAttribute(gemm_kernel<2>,
                         cudaFuncAttributeMaxDynamicSharedMemorySize, SM_TOTAL);

    wsplit_kernel<<<1024, 256>>>(W[0], W[1], W[2], W[3], whi, wlo);

    dim3 ggrid(13, 2, NN);

    // layer 0: res = x (dense 25), out = r0 (padded)
    mix_kernel<<<NROWS / 256, 256>>>(x, A, yh, 25);
    gemm_kernel<0><<<ggrid, 256, SM_TOTAL>>>(yh, whi + 0 * CC * CC,
                                             wlo + 0 * CC * CC, B[0], x, r0);
    // layer 1: padded -> padded (r0 -> r1)
    mix_kernel<<<NROWS / 256, 256>>>(r0, A, yh, 26);
    gemm_kernel<1><<<ggrid, 256, SM_TOTAL>>>(yh, whi + 1 * CC * CC,
                                             wlo + 1 * CC * CC, B[1], r0, r1);
    // layer 2: padded -> padded (r1 -> r0)
    mix_kernel<<<NROWS / 256, 256>>>(r1, A, yh, 26);
    gemm_kernel<1><<<ggrid, 256, SM_TOTAL>>>(yh, whi + 2 * CC * CC,
                                             wlo + 2 * CC * CC, B[2], r1, r0);
    // layer 3: padded -> dense out
    mix_kernel<<<NROWS / 256, 256>>>(r0, A, yh, 26);
    gemm_kernel<2><<<ggrid, 256, SM_TOTAL>>>(yh, whi + 3 * CC * CC,
                                             wlo + 3 * CC * CC, B[3], r0, out);
}